// round 5
// baseline (speedup 1.0000x reference)
#include <cuda_runtime.h>
#include <math.h>

#define Gg   256
#define Nn   512
#define Ee   4096
#define FIN  64
#define FOUT 64
#define Cc   16
#define NK   (Nn * FOUT)          // 32768 flat features per graph
#define HN   256                  // nodes per k2 block (half graph)
#define HCSR (Ee + HN)            // worst-case CSR entries per half

// ---------------- scratch ----------------
__device__ float g_xw[(size_t)Gg * Nn * FOUT];     // x @ W^T
__device__ float g_h [(size_t)Gg * Nn * FOUT];     // relu(aggregate + bias)
__device__ float g_logits[(size_t)Gg * Cc];        // split-K partial logits

// ---------------------------------------------------------------------------
// K1: xw[g] = x[g] @ W^T.  Tile 256 nodes x 64 outs, 8x8 per thread.
//     1.0 B(shared)/FMA -> FFMA-bound.  Dynamic smem 84 KB, 2 blocks/SM.
// ---------------------------------------------------------------------------
#define XPITCH 260
__global__ __launch_bounds__(256) void k1_xw(const float* __restrict__ x,
                                             const float* __restrict__ w)
{
    extern __shared__ float sm[];
    float* Xt = sm;                    // [64][XPITCH]  Xt[k][n]
    float* Wt = sm + 64 * XPITCH;      // [64][68]      Wt[k][o]

    const int g  = blockIdx.y;
    const int nb = blockIdx.x * 256;
    const int t  = threadIdx.x;

    const float* xg = x + ((size_t)g * Nn + nb) * FIN;

    for (int i = t; i < 256 * 64; i += 256) {
        int r = i >> 6, k = i & 63;
        Xt[k * XPITCH + r] = xg[r * FIN + k];
    }
    for (int i = t; i < 64 * 64; i += 256) {
        int o = i >> 6, k = i & 63;
        Wt[k * 68 + o] = w[o * FIN + k];
    }
    __syncthreads();

    const int n0 = (t & 31) * 4;       // lane-minor: conflict-free x reads
    const int o0 = (t >> 5) * 4;       // warp-uniform: broadcast w reads

    float acc[8][8];
    #pragma unroll
    for (int i = 0; i < 8; i++)
        #pragma unroll
        for (int j = 0; j < 8; j++) acc[i][j] = 0.f;

    #pragma unroll 4
    for (int k = 0; k < 64; k++) {
        const float* xk = Xt + k * XPITCH;
        const float* wk = Wt + k * 68;
        float4 xa = *(const float4*)(xk + n0);
        float4 xb = *(const float4*)(xk + n0 + 128);
        float4 wa = *(const float4*)(wk + o0);
        float4 wb = *(const float4*)(wk + o0 + 32);
        float xs[8] = {xa.x, xa.y, xa.z, xa.w, xb.x, xb.y, xb.z, xb.w};
        float ws[8] = {wa.x, wa.y, wa.z, wa.w, wb.x, wb.y, wb.z, wb.w};
        #pragma unroll
        for (int i = 0; i < 8; i++)
            #pragma unroll
            for (int j = 0; j < 8; j++)
                acc[i][j] = fmaf(xs[i], ws[j], acc[i][j]);
    }

    float* op = g_xw + ((size_t)g * Nn + nb) * FOUT;
    #pragma unroll
    for (int i = 0; i < 8; i++) {
        const int n = (i < 4) ? (n0 + i) : (n0 + 128 + i - 4);
        *(float4*)(op + (size_t)n * FOUT + o0) =
            make_float4(acc[i][0], acc[i][1], acc[i][2], acc[i][3]);
        *(float4*)(op + (size_t)n * FOUT + o0 + 32) =
            make_float4(acc[i][4], acc[i][5], acc[i][6], acc[i][7]);
    }
}

// ---------------------------------------------------------------------------
// K2: grid (G, 2). Degree count + half-graph CSR in smem, warp-per-node
//     aggregation + bias + ReLU -> h.   (unchanged from R4)
// ---------------------------------------------------------------------------
__global__ __launch_bounds__(512) void k2_agg(const int*   __restrict__ ei,
                                              const float* __restrict__ conv_bias)
{
    __shared__ int   cnt[Nn];
    __shared__ float dinv[Nn];
    __shared__ int   sc[HN];
    __shared__ int   offx[HN + 1];
    __shared__ int   wcur[HN];
    __shared__ int   srow[HCSR];
    __shared__ float snorm[HCSR];
    __shared__ float bias_s[FOUT];

    const int g   = blockIdx.x;
    const int q   = blockIdx.y;
    const int tid = threadIdx.x;

    const int* rowp = ei + (size_t)g * 2 * Ee;
    const int* colp = rowp + Ee;

    cnt[tid] = 1;
    __syncthreads();
    for (int e = tid; e < Ee; e += 512)
        atomicAdd(&cnt[colp[e]], 1);
    __syncthreads();
    dinv[tid] = rsqrtf((float)cnt[tid]);
    __syncthreads();

    if (tid < HN) sc[tid] = cnt[q * HN + tid];
    __syncthreads();
    for (int s = 1; s < HN; s <<= 1) {
        int v = (tid < HN && tid >= s) ? sc[tid - s] : 0;
        __syncthreads();
        if (tid < HN) sc[tid] += v;
        __syncthreads();
    }
    if (tid < HN) {
        const int n    = q * HN + tid;
        const int incl = sc[tid];
        const int excl = incl - cnt[n];
        offx[tid + 1] = incl;
        srow[excl]  = n;
        snorm[excl] = dinv[n] * dinv[n];
        wcur[tid]   = excl + 1;
    }
    if (tid == 0) offx[0] = 0;
    if (tid < FOUT) bias_s[tid] = conv_bias[tid];
    if (q == 0 && tid < Cc) g_logits[g * Cc + tid] = 0.f;
    __syncthreads();

    for (int e = tid; e < Ee; e += 512) {
        int c = colp[e];
        if ((c >> 8) == q) {
            int r   = rowp[e];
            int pos = atomicAdd(&wcur[c & (HN - 1)], 1);
            srow[pos]  = r;
            snorm[pos] = dinv[r] * dinv[c];
        }
    }
    __syncthreads();

    const float2* xw2 = (const float2*)(g_xw + (size_t)g * NK);
    float2*       h2  = (float2*)      (g_h  + (size_t)g * NK);
    const int wid  = tid >> 5;
    const int lane = tid & 31;
    const float bx0 = bias_s[lane * 2];
    const float bx1 = bias_s[lane * 2 + 1];

    for (int ln = wid; ln < HN; ln += 16) {
        const int n  = q * HN + ln;
        const int b  = offx[ln];
        const int e2 = offx[ln + 1];

        float a0x = 0.f, a0y = 0.f, a1x = 0.f, a1y = 0.f;
        float a2x = 0.f, a2y = 0.f, a3x = 0.f, a3y = 0.f;
        int j = b;
        for (; j + 4 <= e2; j += 4) {
            int   r0 = srow[j],   r1 = srow[j+1], r2 = srow[j+2], r3 = srow[j+3];
            float m0 = snorm[j],  m1 = snorm[j+1], m2 = snorm[j+2], m3 = snorm[j+3];
            float2 v0 = __ldg(&xw2[r0 * 32 + lane]);
            float2 v1 = __ldg(&xw2[r1 * 32 + lane]);
            float2 v2 = __ldg(&xw2[r2 * 32 + lane]);
            float2 v3 = __ldg(&xw2[r3 * 32 + lane]);
            a0x = fmaf(v0.x, m0, a0x);  a0y = fmaf(v0.y, m0, a0y);
            a1x = fmaf(v1.x, m1, a1x);  a1y = fmaf(v1.y, m1, a1y);
            a2x = fmaf(v2.x, m2, a2x);  a2y = fmaf(v2.y, m2, a2y);
            a3x = fmaf(v3.x, m3, a3x);  a3y = fmaf(v3.y, m3, a3y);
        }
        for (; j < e2; j++) {
            int   r  = srow[j];
            float nm = snorm[j];
            float2 v = __ldg(&xw2[r * 32 + lane]);
            a0x = fmaf(v.x, nm, a0x);  a0y = fmaf(v.y, nm, a0y);
        }
        float ax = (a0x + a1x) + (a2x + a3x);
        float ay = (a0y + a1y) + (a2y + a3y);
        ax = fmaxf(ax + bx0, 0.f);
        ay = fmaxf(ay + bx1, 0.f);
        h2[n * 32 + lane] = make_float2(ax, ay);
    }
}

// ---------------------------------------------------------------------------
// K3: logits += h[G,32768] @ lw[C,32768]^T
//     Block = 8 graphs x 512-float4 k-chunk. Warp = 2 graphs x half-chunk.
//     All loads fully-coalesced LDG.128; lw reused across 4 warps via L1.
//     grid (16 ksplit, 32 gtiles), block 256.
// ---------------------------------------------------------------------------
__global__ __launch_bounds__(256) void k3_cls(const float* __restrict__ lw)
{
    __shared__ float red[8][32];

    const int tid  = threadIdx.x;
    const int wid  = tid >> 5;
    const int lane = tid & 31;

    const int ggrp = wid & 3;                 // graph pair 0..3
    const int kq   = wid >> 2;                // k half 0..1
    const int g0   = blockIdx.y * 8 + ggrp * 2;

    // block k-range = 512 float4; warp covers 256 float4 (8 iters of 32)
    const int k4w = blockIdx.x * 512 + kq * 256;

    const float4* h4a = (const float4*)(g_h + (size_t)(g0    ) * NK);
    const float4* h4b = (const float4*)(g_h + (size_t)(g0 + 1) * NK);
    const float4* lw4 = (const float4*)lw;

    float acc[2][Cc];
    #pragma unroll
    for (int p = 0; p < 2; p++)
        #pragma unroll
        for (int c = 0; c < Cc; c++) acc[p][c] = 0.f;

    #pragma unroll 2
    for (int j = 0; j < 8; j++) {
        const int k4 = k4w + j * 32 + lane;
        float4 ha = __ldg(&h4a[k4]);
        float4 hb = __ldg(&h4b[k4]);
        #pragma unroll
        for (int c = 0; c < Cc; c++) {
            float4 wv = __ldg(&lw4[(size_t)c * (NK / 4) + k4]);
            acc[0][c] = fmaf(ha.x, wv.x, fmaf(ha.y, wv.y,
                        fmaf(ha.z, wv.z, fmaf(ha.w, wv.w, acc[0][c]))));
            acc[1][c] = fmaf(hb.x, wv.x, fmaf(hb.y, wv.y,
                        fmaf(hb.z, wv.z, fmaf(hb.w, wv.w, acc[1][c]))));
        }
    }

    #pragma unroll
    for (int p = 0; p < 2; p++)
        #pragma unroll
        for (int c = 0; c < Cc; c++) {
            float v = acc[p][c];
            #pragma unroll
            for (int o = 16; o > 0; o >>= 1)
                v += __shfl_xor_sync(0xffffffffu, v, o);
            acc[p][c] = v;
        }

    if (lane == 0) {
        #pragma unroll
        for (int p = 0; p < 2; p++)
            #pragma unroll
            for (int c = 0; c < Cc; c++)
                red[wid][p * Cc + c] = acc[p][c];
    }
    __syncthreads();

    // tid < 128 : (gi 0..7, c 0..15); warps {ggrp, ggrp+4} contribute
    if (tid < 128) {
        const int gi = tid >> 4;
        const int c  = tid & 15;
        const int gg = gi >> 1;
        const int p  = gi & 1;
        float s = red[gg][p * Cc + c] + red[gg + 4][p * Cc + c];
        atomicAdd(&g_logits[(size_t)(blockIdx.y * 8 + gi) * Cc + c], s);
    }
}

// ---------------------------------------------------------------------------
// K4: bias + log_softmax over [G, 16]
// ---------------------------------------------------------------------------
__global__ __launch_bounds__(256) void k4_lsm(const float* __restrict__ lb,
                                              float* __restrict__ out)
{
    const int tid = threadIdx.x;
    const int g   = blockIdx.x * 16 + (tid >> 4);
    const int c   = tid & 15;

    float s = g_logits[g * Cc + c] + lb[c];
    float m = s;
    #pragma unroll
    for (int o = 8; o > 0; o >>= 1)
        m = fmaxf(m, __shfl_xor_sync(0xffffffffu, m, o, 16));
    float se = expf(s - m);
    #pragma unroll
    for (int o = 8; o > 0; o >>= 1)
        se += __shfl_xor_sync(0xffffffffu, se, o, 16);
    out[g * Cc + c] = (s - m) - logf(se);
}

// ---------------------------------------------------------------------------
extern "C" void kernel_launch(void* const* d_in, const int* in_sizes, int n_in,
                              void* d_out, int out_size)
{
    const float* x  = (const float*)d_in[0];   // [G, N, F_IN]
    const int*   ei = (const int*)  d_in[1];   // [G, 2, E]
    const float* cw = (const float*)d_in[2];   // [F_OUT, F_IN]
    const float* cb = (const float*)d_in[3];   // [F_OUT]
    const float* lw = (const float*)d_in[4];   // [C, N*F_OUT]
    const float* lb = (const float*)d_in[5];   // [C]
    float* out = (float*)d_out;                // [G, C]

    const int k1_smem = (64 * XPITCH + 64 * 68) * sizeof(float);  // 84 KB
    cudaFuncSetAttribute(k1_xw, cudaFuncAttributeMaxDynamicSharedMemorySize,
                         k1_smem);

    k1_xw <<<dim3(Nn / 256, Gg), 256, k1_smem>>>(x, cw);
    k2_agg<<<dim3(Gg, 2), 512>>>(ei, cb);
    k3_cls<<<dim3(16, Gg / 8), 256>>>(lw);
    k4_lsm<<<Gg / 16, 256>>>(lb, out);
}